// round 7
// baseline (speedup 1.0000x reference)
#include <cuda_runtime.h>
#include <math.h>

// NTXentLoss: B=2048, P=16, N=128, D=512 (fp32).
// R7: occupancy + wave-structure attack.
//   - __launch_bounds__(256,6): regs<=42 -> 6 blocks/SM = 48 warps (75% occ)
//   - persistent grid of 888 blocks (148*6), each loops over anchors -> 1 wave,
//     no 2.77-wave tail, prologues overlap across 6 resident blocks
//   - valid-only streaming, positive row folded into row loop, deferred epilogue

#define DDIM 512
#define D4 (DDIM / 4)        // 128 float4 per row
#define THREADS 256
#define NWARPS (THREADS / 32)   // 8
#define TEMP_INV 10.0f
#define COS_EPS 1e-8f
#define GRID_BLOCKS 888         // 148 SMs * 6 blocks/SM

// scratch (no cudaMalloc allowed)
__device__ float g_loss[4096];
__device__ unsigned int g_count = 0;

__device__ __forceinline__ float warpReduceSum(float v) {
#pragma unroll
    for (int o = 16; o; o >>= 1) v += __shfl_down_sync(0xffffffffu, v, o);
    return v;
}

__device__ __forceinline__ float warpReduceMax(float v) {
#pragma unroll
    for (int o = 16; o; o >>= 1) v = fmaxf(v, __shfl_down_sync(0xffffffffu, v, o));
    return v;
}

// Result valid in thread 0 only. Caller must __syncthreads() between reuses of sbuf.
__device__ __forceinline__ float blockReduceSum(float v, float* sbuf) {
    int lane = threadIdx.x & 31, wid = threadIdx.x >> 5;
    v = warpReduceSum(v);
    if (lane == 0) sbuf[wid] = v;
    __syncthreads();
    v = (threadIdx.x < NWARPS) ? sbuf[threadIdx.x] : 0.0f;
    if (wid == 0) {
#pragma unroll
        for (int o = NWARPS / 2; o; o >>= 1) v += __shfl_down_sync(0xffffffffu, v, o);
    }
    return v;
}

__device__ __forceinline__ float blockReduceMax(float v, float* sbuf) {
    int lane = threadIdx.x & 31, wid = threadIdx.x >> 5;
    v = warpReduceMax(v);
    if (lane == 0) sbuf[wid] = v;
    __syncthreads();
    v = (threadIdx.x < NWARPS) ? sbuf[threadIdx.x] : -INFINITY;
    if (wid == 0) {
#pragma unroll
        for (int o = NWARPS / 2; o; o >>= 1) v = fmaxf(v, __shfl_down_sync(0xffffffffu, v, o));
    }
    return v;
}

__global__ void __launch_bounds__(THREADS, 6)
ntxent_main_kernel(const float* __restrict__ target,
                   const float* __restrict__ positives,
                   const float* __restrict__ negatives,
                   const int* __restrict__ pos_idx,
                   const int* __restrict__ neg_mask,
                   float* __restrict__ out,
                   int B, int P, int N) {
    const int tid = threadIdx.x;
    const int lane = tid & 31;
    const int w = tid >> 5;

    __shared__ float4 s_tgt[D4];      // 2KB target row
    __shared__ float s_dot[132];      // raw dots: [0..M-1]=negs, [M]=pos
    __shared__ float s_q[132];        // raw squared norms
    __shared__ int   s_valid[132];    // compacted valid negative indices
    __shared__ int   s_wcnt[NWARPS];
    __shared__ float s_red[NWARPS];
    __shared__ float s_bcast[4];
    __shared__ int   s_islast;

    for (int b = blockIdx.x; b < B; b += gridDim.x) {
        // --- compact valid negative indices (deterministic prefix via ballot) ---
        int mvalid = 0;
        if (tid < N) mvalid = (neg_mask[(size_t)b * N + tid] != 0);
        unsigned bal = __ballot_sync(0xffffffffu, mvalid);
        if (lane == 0) s_wcnt[w] = __popc(bal);

        // --- load target row into SMEM; |t|^2 partial in a register ---
        float tq = 0.0f;
        if (tid < D4) {
            float4 tv = ((const float4*)(target + (size_t)b * DDIM))[tid];
            s_tgt[tid] = tv;
            tq = tv.x * tv.x + tv.y * tv.y + tv.z * tv.z + tv.w * tv.w;
        }
        const int pi = pos_idx[b];
        __syncthreads();   // s_tgt + s_wcnt ready

        int off = 0, M = 0;
#pragma unroll
        for (int j = 0; j < NWARPS; j++) {
            int c = s_wcnt[j];
            if (j < w) off += c;
            M += c;
        }
        if (mvalid) s_valid[off + __popc(bal & ((1u << lane) - 1u))] = tid;
        __syncthreads();   // s_valid ready

        // --- stream rows: valid negatives + positive as row M ---
        const float4* negb = (const float4*)(negatives + (size_t)b * (size_t)N * DDIM);
        const float4* posr = (const float4*)(positives + ((size_t)b * P + pi) * (size_t)DDIM);
        const int R = M + 1;

        for (int i = w; i < R; i += NWARPS) {
            const float4* v = (i < M) ? (negb + (size_t)s_valid[i] * D4) : posr;
            float dot = 0.0f, q = 0.0f;
#pragma unroll
            for (int k = 0; k < 4; k++) {   // 4 front-batched LDG.128
                float4 x = v[lane + 32 * k];
                float4 t = s_tgt[lane + 32 * k];
                dot = fmaf(x.x, t.x, dot); dot = fmaf(x.y, t.y, dot);
                dot = fmaf(x.z, t.z, dot); dot = fmaf(x.w, t.w, dot);
                q = fmaf(x.x, x.x, q); q = fmaf(x.y, x.y, q);
                q = fmaf(x.z, x.z, q); q = fmaf(x.w, x.w, q);
            }
            dot = warpReduceSum(dot);
            q = warpReduceSum(q);
            if (lane == 0) { s_dot[i] = dot; s_q[i] = q; }
        }
        __syncthreads();

        // --- epilogue: ||t||, sims, LSE ---
        float tsum = blockReduceSum(tq, s_red);
        if (tid == 0) s_bcast[0] = sqrtf(tsum);
        __syncthreads();
        const float tnorm = s_bcast[0];

        float x = -INFINITY;
        if (tid < M)
            x = (s_dot[tid] / fmaxf(sqrtf(s_q[tid]) * tnorm, COS_EPS)) * TEMP_INV;
        const float pos_sim =
            (s_dot[M] / fmaxf(sqrtf(s_q[M]) * tnorm, COS_EPS)) * TEMP_INV;

        float m = blockReduceMax(fmaxf(x, pos_sim), s_red);
        if (tid == 0) s_bcast[2] = m;
        __syncthreads();
        m = s_bcast[2];
        float e = (x == -INFINITY) ? 0.0f : expf(x - m);
        if (tid == 0) e += expf(pos_sim - m);   // fold positive term
        __syncthreads();  // protect s_red reuse
        float S = blockReduceSum(e, s_red);

        // --- publish per-anchor loss; globally-last finisher reduces mean ---
        if (tid == 0) {
            g_loss[b] = logf(S) + m - pos_sim;
            __threadfence();
            unsigned int old = atomicAdd(&g_count, 1u);
            s_islast = (old == (unsigned int)(B - 1));
        }
        __syncthreads();
        if (s_islast) {
            __threadfence();
            float v = 0.0f;
            for (int i = tid; i < B; i += THREADS) v += g_loss[i];
            __syncthreads();  // s_red safe to reuse
            v = blockReduceSum(v, s_red);
            if (tid == 0) {
                out[0] = v / (float)B;
                g_count = 0;  // reset for next graph replay
            }
        }
        __syncthreads();  // smem safe for next anchor iteration
    }
}

extern "C" void kernel_launch(void* const* d_in, const int* in_sizes, int n_in,
                              void* d_out, int out_size) {
    const float* target = (const float*)d_in[0];
    const float* positives = (const float*)d_in[1];
    const float* negatives = (const float*)d_in[2];
    const int* pos_idx = (const int*)d_in[3];
    const int* neg_mask = (const int*)d_in[4];
    float* out = (float*)d_out;

    const int B = in_sizes[0] / DDIM;                 // 2048
    const int P = in_sizes[1] / in_sizes[0];          // 16
    const int N = in_sizes[2] / in_sizes[0];          // 128

    int grid = GRID_BLOCKS < B ? GRID_BLOCKS : B;
    ntxent_main_kernel<<<grid, THREADS>>>(target, positives, negatives, pos_idx,
                                          neg_mask, out, B, P, N);
}

// round 8
// speedup vs baseline: 1.3823x; 1.3823x over previous
#include <cuda_runtime.h>
#include <math.h>

// NTXentLoss: B=2048, P=16, N=128, D=512 (fp32).
// R8: software-pipelined row streaming — next row's 4 LDG.128 are issued
//     BEFORE the current row's FMA + shuffle-reduce chain, so loads stay in
//     flight through the compute tail (R4-R7 plateau at DRAM~60% was per-warp
//     load duty cycle). grid=2048, 256 thr, 5 blocks/SM, deferred epilogue.

#define DDIM 512
#define D4 (DDIM / 4)        // 128 float4 per row
#define THREADS 256
#define NWARPS (THREADS / 32)   // 8
#define TEMP_INV 10.0f
#define COS_EPS 1e-8f

// scratch (no cudaMalloc allowed)
__device__ float g_loss[4096];
__device__ unsigned int g_count = 0;

__device__ __forceinline__ float warpReduceSum(float v) {
#pragma unroll
    for (int o = 16; o; o >>= 1) v += __shfl_down_sync(0xffffffffu, v, o);
    return v;
}

__device__ __forceinline__ float warpReduceMax(float v) {
#pragma unroll
    for (int o = 16; o; o >>= 1) v = fmaxf(v, __shfl_down_sync(0xffffffffu, v, o));
    return v;
}

// Result valid in thread 0 only. Caller must __syncthreads() between reuses of sbuf.
__device__ __forceinline__ float blockReduceSum(float v, float* sbuf) {
    int lane = threadIdx.x & 31, wid = threadIdx.x >> 5;
    v = warpReduceSum(v);
    if (lane == 0) sbuf[wid] = v;
    __syncthreads();
    v = (threadIdx.x < NWARPS) ? sbuf[threadIdx.x] : 0.0f;
    if (wid == 0) {
#pragma unroll
        for (int o = NWARPS / 2; o; o >>= 1) v += __shfl_down_sync(0xffffffffu, v, o);
    }
    return v;
}

__device__ __forceinline__ float blockReduceMax(float v, float* sbuf) {
    int lane = threadIdx.x & 31, wid = threadIdx.x >> 5;
    v = warpReduceMax(v);
    if (lane == 0) sbuf[wid] = v;
    __syncthreads();
    v = (threadIdx.x < NWARPS) ? sbuf[threadIdx.x] : -INFINITY;
    if (wid == 0) {
#pragma unroll
        for (int o = NWARPS / 2; o; o >>= 1) v = fmaxf(v, __shfl_down_sync(0xffffffffu, v, o));
    }
    return v;
}

__global__ void __launch_bounds__(THREADS, 5)
ntxent_main_kernel(const float* __restrict__ target,
                   const float* __restrict__ positives,
                   const float* __restrict__ negatives,
                   const int* __restrict__ pos_idx,
                   const int* __restrict__ neg_mask,
                   float* __restrict__ out,
                   int B, int P, int N) {
    const int b = blockIdx.x;
    const int tid = threadIdx.x;
    const int lane = tid & 31;
    const int w = tid >> 5;

    __shared__ float4 s_tgt[D4];      // 2KB target row
    __shared__ float s_dot[132];      // raw dots: [0..M-1]=negs, [M]=pos
    __shared__ float s_q[132];        // raw squared norms
    __shared__ int   s_valid[132];    // compacted valid negative indices
    __shared__ int   s_wcnt[NWARPS];
    __shared__ float s_red[NWARPS];
    __shared__ float s_bcast[4];
    __shared__ int   s_islast;

    // --- compact valid negative indices (deterministic prefix via ballot) ---
    int mvalid = 0;
    if (tid < N) mvalid = (neg_mask[(size_t)b * N + tid] != 0);
    unsigned bal = __ballot_sync(0xffffffffu, mvalid);
    if (lane == 0) s_wcnt[w] = __popc(bal);

    // --- load target row into SMEM; |t|^2 partial in a register ---
    float tq = 0.0f;
    if (tid < D4) {
        float4 tv = ((const float4*)(target + (size_t)b * DDIM))[tid];
        s_tgt[tid] = tv;
        tq = tv.x * tv.x + tv.y * tv.y + tv.z * tv.z + tv.w * tv.w;
    }
    const int pi = pos_idx[b];
    __syncthreads();   // s_tgt + s_wcnt ready

    int off = 0, M = 0;
#pragma unroll
    for (int j = 0; j < NWARPS; j++) {
        int c = s_wcnt[j];
        if (j < w) off += c;
        M += c;
    }
    if (mvalid) s_valid[off + __popc(bal & ((1u << lane) - 1u))] = tid;
    __syncthreads();   // s_valid ready

    // --- software-pipelined row streaming: valid negatives + positive (row M) ---
    const float4* negb = (const float4*)(negatives + (size_t)b * (size_t)N * DDIM);
    const float4* posr = (const float4*)(positives + ((size_t)b * P + pi) * (size_t)DDIM);
    const int R = M + 1;

    int i = w;
    if (i < R) {
        const float4* vc = (i < M) ? (negb + (size_t)s_valid[i] * D4) : posr;
        float4 cur[4];
#pragma unroll
        for (int k = 0; k < 4; k++) cur[k] = vc[lane + 32 * k];

        for (; i < R; i += NWARPS) {
            // prefetch NEXT row before computing current (keeps LDGs in flight
            // through the FMA + shuffle chains)
            const int j = i + NWARPS;
            const float4* vn = (j < R) ? ((j < M) ? (negb + (size_t)s_valid[j] * D4) : posr)
                                       : vc;
            float4 nxt[4];
#pragma unroll
            for (int k = 0; k < 4; k++) nxt[k] = vn[lane + 32 * k];

            float dot = 0.0f, q = 0.0f;
#pragma unroll
            for (int k = 0; k < 4; k++) {
                float4 t = s_tgt[lane + 32 * k];
                dot = fmaf(cur[k].x, t.x, dot); dot = fmaf(cur[k].y, t.y, dot);
                dot = fmaf(cur[k].z, t.z, dot); dot = fmaf(cur[k].w, t.w, dot);
                q = fmaf(cur[k].x, cur[k].x, q); q = fmaf(cur[k].y, cur[k].y, q);
                q = fmaf(cur[k].z, cur[k].z, q); q = fmaf(cur[k].w, cur[k].w, q);
            }
            dot = warpReduceSum(dot);
            q = warpReduceSum(q);
            if (lane == 0) { s_dot[i] = dot; s_q[i] = q; }

#pragma unroll
            for (int k = 0; k < 4; k++) cur[k] = nxt[k];
            vc = vn;
        }
    }
    __syncthreads();

    // --- epilogue: ||t||, sims, LSE ---
    float tsum = blockReduceSum(tq, s_red);
    if (tid == 0) s_bcast[0] = sqrtf(tsum);
    __syncthreads();
    const float tnorm = s_bcast[0];

    float x = -INFINITY;
    if (tid < M)
        x = (s_dot[tid] / fmaxf(sqrtf(s_q[tid]) * tnorm, COS_EPS)) * TEMP_INV;
    const float pos_sim =
        (s_dot[M] / fmaxf(sqrtf(s_q[M]) * tnorm, COS_EPS)) * TEMP_INV;

    float m = blockReduceMax(fmaxf(x, pos_sim), s_red);
    if (tid == 0) s_bcast[2] = m;
    __syncthreads();
    m = s_bcast[2];
    float e = (x == -INFINITY) ? 0.0f : expf(x - m);
    if (tid == 0) e += expf(pos_sim - m);   // fold positive term
    __syncthreads();  // protect s_red reuse
    float S = blockReduceSum(e, s_red);

    // --- publish per-anchor loss; last finisher reduces the mean ---
    if (tid == 0) {
        g_loss[b] = logf(S) + m - pos_sim;
        __threadfence();
        unsigned int old = atomicAdd(&g_count, 1u);
        s_islast = (old == (unsigned int)(B - 1));
    }
    __syncthreads();
    if (s_islast) {
        __threadfence();
        float v = 0.0f;
        for (int k = tid; k < B; k += THREADS) v += g_loss[k];
        __syncthreads();  // s_red safe to reuse
        v = blockReduceSum(v, s_red);
        if (tid == 0) {
            out[0] = v / (float)B;
            g_count = 0;  // reset for next graph replay
        }
    }
}

extern "C" void kernel_launch(void* const* d_in, const int* in_sizes, int n_in,
                              void* d_out, int out_size) {
    const float* target = (const float*)d_in[0];
    const float* positives = (const float*)d_in[1];
    const float* negatives = (const float*)d_in[2];
    const int* pos_idx = (const int*)d_in[3];
    const int* neg_mask = (const int*)d_in[4];
    float* out = (float*)d_out;

    const int B = in_sizes[0] / DDIM;                 // 2048
    const int P = in_sizes[1] / in_sizes[0];          // 16
    const int N = in_sizes[2] / in_sizes[0];          // 128

    ntxent_main_kernel<<<B, THREADS>>>(target, positives, negatives, pos_idx,
                                       neg_mask, out, B, P, N);
}